// round 14
// baseline (speedup 1.0000x reference)
#include <cuda_runtime.h>
#include <cstdint>

#define B_  8
#define N_  512
#define F_  32
#define BN_ (B_ * N_)

#define STAGE_J     64                       // j's per pipeline stage
#define STAGE_BYTES (STAGE_J * F_ * 4)       // 8192 B
#define NBUF        4                        // SMEM ring buffers
#define NSTAGES     (N_ / STAGE_J)           // 8 stages per row
#define DEPTH       3                        // fills in flight (safe ordering)

#define PREPB       512                      // leading prep blocks (8 rows ea)
#define CHUNK_PREPB 8                        // prep blocks per (batch,chunk)

// Scratch (allocation-free rule: __device__ globals; zero-init at load,
// self-reset in-kernel so every graph replay sees zeros)
__device__ float g_x1[BN_ * F_];
__device__ unsigned int g_ck[B_][NSTAGES];   // per-(batch,chunk) prep arrivals
__device__ unsigned int g_done[B_];          // per-batch agg completions

__device__ __forceinline__ uint32_t smem_u32(const void* p) {
    return (uint32_t)__cvta_generic_to_shared(p);
}

// ---------------------------------------------------------------------------
// Fused kernel, stage-granular dependency.
//  blocks [0, PREPB): prep — warp per row (8 rows = one 64-row chunk):
//      g_x1 = mlp_n(x); outX2 = mlp_s(x); fence; arrive g_ck[batch][chunk].
//  blocks [PREPB, PREPB+BN_): agg for row bi:
//      x1-independent prologue (mbar init, DEPTH TMA fills, A row-sum);
//      stage s polls g_ck[b][s] >= 8 (chunk producers are wave-1 resident,
//      scheduled first) -> FROZEN stream loop -> epilogue RMW;
//      last agg block of each batch resets that batch's counters.
// ---------------------------------------------------------------------------
__global__ __launch_bounds__(256)
void fused_kernel(const float* __restrict__ A, const float* __restrict__ W,
                  const float* __restrict__ x,
                  const float* __restrict__ Wn1, const float* __restrict__ bn1,
                  const float* __restrict__ Wn2, const float* __restrict__ bn2,
                  const float* __restrict__ Ws1, const float* __restrict__ bs1,
                  const float* __restrict__ Ws2, const float* __restrict__ bs2,
                  float* __restrict__ outW, float* __restrict__ outX2) {
    __shared__ __align__(128) float sbuf[NBUF][STAGE_J * F_];   // 32 KB
    __shared__ __align__(8) unsigned long long mbar[NBUF];
    __shared__ float sacc[8][F_];
    __shared__ float s_ws[8];
    __shared__ float s_inv;

    const unsigned FULL = 0xffffffffu;
    int tid  = threadIdx.x;
    int warp = tid >> 5;
    int lane = tid & 31;

    // ===================== PREP BLOCKS =====================
    if (blockIdx.x < PREPB) {
        int row = blockIdx.x * 8 + warp;      // 8 warps = 8 rows = one chunk
        int f   = lane;

        float xv = x[row * F_ + f];

        float h  = bn1[f];
        float hs = bs1[f];
        #pragma unroll
        for (int k = 0; k < F_; k++) {
            float xk = __shfl_sync(FULL, xv, k);
            h  = fmaf(xk, Wn1[k * F_ + f], h);
            hs = fmaf(xk, Ws1[k * F_ + f], hs);
        }
        h  = fmaxf(h, 0.0f);
        hs = fmaxf(hs, 0.0f);

        float o1 = bn2[f];
        float o2 = bs2[f];
        #pragma unroll
        for (int k = 0; k < F_; k++) {
            o1 = fmaf(__shfl_sync(FULL, h,  k), Wn2[k * F_ + f], o1);
            o2 = fmaf(__shfl_sync(FULL, hs, k), Ws2[k * F_ + f], o2);
        }
        g_x1[row * F_ + f]  = fmaxf(o1, 0.0f);
        outX2[row * F_ + f] = fmaxf(o2, 0.0f);

        __threadfence();          // release: publish rows before arrive
        __syncthreads();
        if (tid == 0) {
            int batch = (int)(blockIdx.x >> 6);        // 64 blocks per batch
            int chunk = (int)((blockIdx.x >> 3) & 7);  // 8 blocks per chunk
            atomicAdd(&g_ck[batch][chunk], 1u);
        }
        return;
    }

    // ===================== AGG BLOCKS =====================
    int bi = (int)blockIdx.x - PREPB;  // row (b*N + i)
    int b  = bi >> 9;                  // N_ = 512
    int fq = lane & 7;
    int jo = lane >> 3;

    const char* Wrow = (const char*)(W    + (size_t)bi * N_ * F_);
    char*       Orow = (char*)      (outW + (size_t)bi * N_ * F_);
    const float4* x1p  = (const float4*)(g_x1 + (size_t)b * N_ * F_);
    const float*  Arow = A + (size_t)bi * N_;

    uint32_t sbuf_s = smem_u32(&sbuf[0][0]);
    uint32_t mbar_s = smem_u32(&mbar[0]);

    if (tid == 0) {
        #pragma unroll
        for (int i = 0; i < NBUF; i++)
            asm volatile("mbarrier.init.shared::cta.b64 [%0], 1;"
                         :: "r"(mbar_s + i * 8) : "memory");
    }
    __syncthreads();

    // prologue A: fill stages 0..DEPTH-1 (reads only W)
    if (tid == 0) {
        #pragma unroll
        for (int s = 0; s < DEPTH; s++) {
            uint32_t mb = mbar_s + s * 8;
            asm volatile("mbarrier.arrive.expect_tx.shared::cta.b64 _, [%0], %1;"
                         :: "r"(mb), "r"((uint32_t)STAGE_BYTES) : "memory");
            asm volatile(
                "cp.async.bulk.shared::cluster.global.mbarrier::complete_tx::bytes"
                " [%0], [%1], %2, [%3];"
                :: "r"(sbuf_s + s * STAGE_BYTES),
                   "l"(Wrow + (size_t)s * STAGE_BYTES),
                   "r"((uint32_t)STAGE_BYTES), "r"(mb) : "memory");
        }
    }

    // prologue B: A row-sum (reads only A; warms L1 for the loop's A loads)
    {
        float as = 0.0f;
        if (tid < 128) {                       // 128 float4 = 512 floats
            float4 av = ((const float4*)Arow)[tid];
            as = (av.x + av.y) + (av.z + av.w);
        }
        #pragma unroll
        for (int o = 16; o; o >>= 1) as += __shfl_xor_sync(FULL, as, o);
        if (lane == 0) s_ws[warp] = as;
        __syncthreads();
        if (tid == 0) {
            float rowsum = s_ws[0] + s_ws[1] + s_ws[2] + s_ws[3];
            s_inv = 1.0f / fmaxf(rowsum, 1e-12f);
        }
    }

    float4 acc = make_float4(0.0f, 0.0f, 0.0f, 0.0f);

    for (int s = 0; s < NSTAGES; s++) {
        int p = s & (NBUF - 1);
        uint32_t mb  = mbar_s + p * 8;
        uint32_t phs = (uint32_t)((s >> 2) & 1);

        // consumer wait (acquire) -- TMA fill for stage s complete
        {
            uint32_t done;
            asm volatile(
                "{ .reg .pred q;\n\t"
                "mbarrier.try_wait.parity.acquire.cta.shared::cta.b64 q, [%1], %2;\n\t"
                "selp.b32 %0, 1, 0, q; }"
                : "=r"(done) : "r"(mb), "r"(phs) : "memory");
            if (!done) {
                asm volatile(
                    "{ .reg .pred q;\n\t"
                    "WL_%=:\n\t"
                    "mbarrier.try_wait.parity.acquire.cta.shared::cta.b64 q, [%0], %1, 0x989680;\n\t"
                    "@q bra.uni WD_%=;\n\t"
                    "bra.uni WL_%=;\n\t"
                    "WD_%=: }"
                    :: "r"(mb), "r"(phs) : "memory");
            }
        }

        // x1 dependency: chunk s of this batch (8 prep blocks, wave-1 first)
        if (tid == 0) {
            const unsigned int* cp = &g_ck[b][s];
            unsigned int v;
            while (true) {
                asm volatile("ld.global.cg.u32 %0, [%1];" : "=r"(v) : "l"(cp));
                if (v >= CHUNK_PREPB) break;
                __nanosleep(64);
            }
            __threadfence();      // acquire: order x1 reads after flag
        }
        __syncthreads();

        uint32_t buf = sbuf_s + p * STAGE_BYTES;

        // compute: warp handles 8 j's of this 64-j stage (2 iters of 4 j)
        #pragma unroll
        for (int k = 0; k < 2; k++) {
            uint32_t a0_, a1_, a2_, a3_;
            asm volatile("ld.shared.v4.b32 {%0,%1,%2,%3}, [%4];"
                         : "=r"(a0_), "=r"(a1_), "=r"(a2_), "=r"(a3_)
                         : "r"(buf + warp * 1024 + k * 512 + lane * 16));
            float4 w4;
            w4.x = __uint_as_float(a0_); w4.y = __uint_as_float(a1_);
            w4.z = __uint_as_float(a2_); w4.w = __uint_as_float(a3_);
            int j = s * STAGE_J + warp * 8 + k * 4 + jo;
            float  a  = __ldg(Arow + j);          // L1-hot (prologue B)
            float4 xv = x1p[j * 8 + fq];          // fully coalesced 512B/warp
            acc.x = fmaf(a * w4.x, xv.x, acc.x);
            acc.y = fmaf(a * w4.y, xv.y, acc.y);
            acc.z = fmaf(a * w4.z, xv.z, acc.z);
            acc.w = fmaf(a * w4.w, xv.w, acc.w);
        }

        __syncthreads();   // all warps done reading buf p

        if (tid == 0) {
            // copy-out this stage (reads SMEM asynchronously)
            asm volatile("cp.async.bulk.global.shared::cta.bulk_group [%0], [%1], %2;"
                         :: "l"(Orow + (size_t)s * STAGE_BYTES),
                            "r"(buf), "r"((uint32_t)STAGE_BYTES) : "memory");
            asm volatile("cp.async.bulk.commit_group;" ::: "memory");

            int s2 = s + DEPTH;
            if (s2 < NSTAGES) {
                // refill target buf (s-1)&3: drain its copy-out group G_{s-1}
                asm volatile("cp.async.bulk.wait_group.read 1;" ::: "memory");
                int p2 = s2 & (NBUF - 1);
                uint32_t mb2 = mbar_s + p2 * 8;
                asm volatile("mbarrier.arrive.expect_tx.shared::cta.b64 _, [%0], %1;"
                             :: "r"(mb2), "r"((uint32_t)STAGE_BYTES) : "memory");
                asm volatile(
                    "cp.async.bulk.shared::cluster.global.mbarrier::complete_tx::bytes"
                    " [%0], [%1], %2, [%3];"
                    :: "r"(sbuf_s + p2 * STAGE_BYTES),
                       "l"(Wrow + (size_t)s2 * STAGE_BYTES),
                       "r"((uint32_t)STAGE_BYTES), "r"(mb2) : "memory");
            }
        }
    }

    // reduce across the 4 lanes sharing a feature-quad (xor 8, 16)
    #pragma unroll
    for (int o = 8; o <= 16; o <<= 1) {
        acc.x += __shfl_xor_sync(FULL, acc.x, o);
        acc.y += __shfl_xor_sync(FULL, acc.y, o);
        acc.z += __shfl_xor_sync(FULL, acc.z, o);
        acc.w += __shfl_xor_sync(FULL, acc.w, o);
    }
    if (lane < 8) {
        sacc[warp][lane * 4 + 0] = acc.x;
        sacc[warp][lane * 4 + 1] = acc.y;
        sacc[warp][lane * 4 + 2] = acc.z;
        sacc[warp][lane * 4 + 3] = acc.w;
    }
    __syncthreads();

    // block owns the full row: plain read-modify-write (prep stored xs here)
    if (tid < F_) {
        float ssum = 0.0f;
        #pragma unroll
        for (int w8 = 0; w8 < 8; w8++) ssum += sacc[w8][tid];
        float* dst = outX2 + (size_t)bi * F_ + tid;
        *dst = fmaf(ssum, s_inv, *dst);
    }

    // counter self-reset: the 512th finishing agg block of each batch zeroes
    // that batch's counters (all consumers already passed every poll).
    __syncthreads();
    if (tid == 0) {
        unsigned int prev = atomicAdd(&g_done[b], 1u);
        if (prev == (unsigned int)(N_ - 1)) {
            #pragma unroll
            for (int c = 0; c < NSTAGES; c++) g_ck[b][c] = 0u;
            g_done[b] = 0u;
            __threadfence();      // publish resets before kernel end
        }
    }
    // bulk stores drain at kernel completion
}

// ---------------------------------------------------------------------------
// Launch. Inputs (metadata order): A, W, x, Wn1, bn1, Wn2, bn2, Ws1, bs1,
// Ws2, bs2. Output: [W (B*N*N*F) | x2 (B*N*F)] as float32.
// Single fused kernel, no memset node (counters self-reset in-kernel).
// ---------------------------------------------------------------------------
extern "C" void kernel_launch(void* const* d_in, const int* in_sizes, int n_in,
                              void* d_out, int out_size) {
    const float* A   = (const float*)d_in[0];
    const float* W   = (const float*)d_in[1];
    const float* x   = (const float*)d_in[2];
    const float* Wn1 = (const float*)d_in[3];
    const float* bn1 = (const float*)d_in[4];
    const float* Wn2 = (const float*)d_in[5];
    const float* bn2 = (const float*)d_in[6];
    const float* Ws1 = (const float*)d_in[7];
    const float* bs1 = (const float*)d_in[8];
    const float* Ws2 = (const float*)d_in[9];
    const float* bs2 = (const float*)d_in[10];

    float* out   = (float*)d_out;
    float* outW  = out;
    float* outX2 = out + (size_t)B_ * N_ * N_ * F_;

    fused_kernel<<<PREPB + BN_, 256>>>(A, W, x, Wn1, bn1, Wn2, bn2,
                                       Ws1, bs1, Ws2, bs2, outW, outX2);
}

// round 15
// speedup vs baseline: 1.0471x; 1.0471x over previous
#include <cuda_runtime.h>
#include <cstdint>

#define B_  8
#define N_  512
#define F_  32
#define BN_ (B_ * N_)

#define STAGE_J     64                       // j's per pipeline stage
#define STAGE_BYTES (STAGE_J * F_ * 4)       // 8192 B
#define NSTAGES     (N_ / STAGE_J)           // 8 stages per row
#define NBUF        NSTAGES                  // full row buffered: no reuse

// Scratch (allocation-free rule: __device__ globals)
__device__ float g_x1[BN_ * F_];

__device__ __forceinline__ uint32_t smem_u32(const void* p) {
    return (uint32_t)__cvta_generic_to_shared(p);
}

// ---------------------------------------------------------------------------
// Prep kernel (proven R12 version): one warp per (b,n) row; x-only.
//  - g_x1  = relu(relu(x@Wn1+bn1)@Wn2+bn2)
//  - outX2 = relu(relu(x@Ws1+bs1)@Ws2+bs2)   (self path; agg adds onto it)
// ---------------------------------------------------------------------------
__global__ __launch_bounds__(256)
void prep_kernel(const float* __restrict__ x,
                 const float* __restrict__ Wn1, const float* __restrict__ bn1,
                 const float* __restrict__ Wn2, const float* __restrict__ bn2,
                 const float* __restrict__ Ws1, const float* __restrict__ bs1,
                 const float* __restrict__ Ws2, const float* __restrict__ bs2,
                 float* __restrict__ outX2) {
    const unsigned FULL = 0xffffffffu;
    int row = blockIdx.x * (blockDim.x >> 5) + (threadIdx.x >> 5);
    int f   = threadIdx.x & 31;
    if (row >= BN_) return;

    float xv = x[row * F_ + f];

    float h  = bn1[f];
    float hs = bs1[f];
    #pragma unroll
    for (int k = 0; k < F_; k++) {
        float xk = __shfl_sync(FULL, xv, k);
        h  = fmaf(xk, Wn1[k * F_ + f], h);
        hs = fmaf(xk, Ws1[k * F_ + f], hs);
    }
    h  = fmaxf(h, 0.0f);
    hs = fmaxf(hs, 0.0f);

    float o1 = bn2[f];
    float o2 = bs2[f];
    #pragma unroll
    for (int k = 0; k < F_; k++) {
        o1 = fmaf(__shfl_sync(FULL, h,  k), Wn2[k * F_ + f], o1);
        o2 = fmaf(__shfl_sync(FULL, hs, k), Ws2[k * F_ + f], o2);
    }
    g_x1[row * F_ + f]  = fmaxf(o1, 0.0f);
    outX2[row * F_ + f] = fmaxf(o2, 0.0f);
}

// ---------------------------------------------------------------------------
// Aggregation + W copy: full-row SMEM buffering, single-use buffers.
//  prologue: mbar init -> ALL 8 TMA fills (64 KB of W) -> A row-sum -> PDL.
//  loop:     per-stage mbar wait (phase 0; each buffer filled exactly once);
//            tid0 issues copy-out immediately after its wait (safe: the only
//            SMEM writer is the completed fill -- no reuse, no race);
//            compute reads SMEM -- NO per-stage __syncthreads, warps fully
//            decoupled. No wait_group, no refill.
//  epilogue: one sync, sacc reduce, RMW of outX2 (prep stored xs there).
// ---------------------------------------------------------------------------
__global__ __launch_bounds__(256)
void agg_kernel(const float* __restrict__ A, const float* __restrict__ W,
                float* __restrict__ outW, float* __restrict__ outX2) {
    __shared__ __align__(128) float sbuf[NBUF][STAGE_J * F_];   // 64 KB
    __shared__ __align__(8) unsigned long long mbar[NBUF];
    __shared__ float sacc[8][F_];
    __shared__ float s_ws[8];
    __shared__ float s_inv;

    const unsigned FULL = 0xffffffffu;
    int bi   = blockIdx.x;            // row (b*N + i)
    int b    = bi >> 9;               // N_ = 512
    int tid  = threadIdx.x;
    int warp = tid >> 5;
    int lane = tid & 31;
    int fq   = lane & 7;
    int jo   = lane >> 3;

    const char* Wrow = (const char*)(W    + (size_t)bi * N_ * F_);
    char*       Orow = (char*)      (outW + (size_t)bi * N_ * F_);
    const float4* x1p  = (const float4*)(g_x1 + (size_t)b * N_ * F_);
    const float*  Arow = A + (size_t)bi * N_;

    uint32_t sbuf_s = smem_u32(&sbuf[0][0]);
    uint32_t mbar_s = smem_u32(&mbar[0]);

    if (tid == 0) {
        #pragma unroll
        for (int i = 0; i < NBUF; i++)
            asm volatile("mbarrier.init.shared::cta.b64 [%0], 1;"
                         :: "r"(mbar_s + i * 8) : "memory");
    }
    __syncthreads();

    // prologue A: issue ALL stage fills (reads only W)
    if (tid == 0) {
        #pragma unroll
        for (int s = 0; s < NSTAGES; s++) {
            uint32_t mb = mbar_s + s * 8;
            asm volatile("mbarrier.arrive.expect_tx.shared::cta.b64 _, [%0], %1;"
                         :: "r"(mb), "r"((uint32_t)STAGE_BYTES) : "memory");
            asm volatile(
                "cp.async.bulk.shared::cluster.global.mbarrier::complete_tx::bytes"
                " [%0], [%1], %2, [%3];"
                :: "r"(sbuf_s + s * STAGE_BYTES),
                   "l"(Wrow + (size_t)s * STAGE_BYTES),
                   "r"((uint32_t)STAGE_BYTES), "r"(mb) : "memory");
        }
    }

    // prologue B: A row-sum (reads only A; warms L1 for the loop's A loads)
    {
        float as = 0.0f;
        if (tid < 128) {                       // 128 float4 = 512 floats
            float4 av = ((const float4*)Arow)[tid];
            as = (av.x + av.y) + (av.z + av.w);
        }
        #pragma unroll
        for (int o = 16; o; o >>= 1) as += __shfl_xor_sync(FULL, as, o);
        if (lane == 0) s_ws[warp] = as;
        __syncthreads();
        if (tid == 0) {
            float rowsum = s_ws[0] + s_ws[1] + s_ws[2] + s_ws[3];
            s_inv = 1.0f / fmaxf(rowsum, 1e-12f);
        }
    }

    // PDL: wait for prep_kernel's writes (g_x1, outX2) to be visible.
    cudaGridDependencySynchronize();

    float4 acc = make_float4(0.0f, 0.0f, 0.0f, 0.0f);

    // barrier-free consume: each buffer filled exactly once -> phase 0
    for (int s = 0; s < NSTAGES; s++) {
        uint32_t mb = mbar_s + s * 8;

        // wait for fill s (acquire); all threads, warp-paced
        {
            uint32_t done;
            asm volatile(
                "{ .reg .pred q;\n\t"
                "mbarrier.try_wait.parity.acquire.cta.shared::cta.b64 q, [%1], 0;\n\t"
                "selp.b32 %0, 1, 0, q; }"
                : "=r"(done) : "r"(mb) : "memory");
            if (!done) {
                asm volatile(
                    "{ .reg .pred q;\n\t"
                    "WL_%=:\n\t"
                    "mbarrier.try_wait.parity.acquire.cta.shared::cta.b64 q, [%0], 0, 0x989680;\n\t"
                    "@q bra.uni WD_%=;\n\t"
                    "bra.uni WL_%=;\n\t"
                    "WD_%=: }"
                    :: "r"(mb) : "memory");
            }
        }

        uint32_t buf = sbuf_s + s * STAGE_BYTES;

        // copy-out immediately (single-use buffer: fill is the only writer)
        if (tid == 0) {
            asm volatile("cp.async.bulk.global.shared::cta.bulk_group [%0], [%1], %2;"
                         :: "l"(Orow + (size_t)s * STAGE_BYTES),
                            "r"(buf), "r"((uint32_t)STAGE_BYTES) : "memory");
            asm volatile("cp.async.bulk.commit_group;" ::: "memory");
        }

        // compute: warp handles 8 j's of this 64-j stage (2 iters of 4 j)
        #pragma unroll
        for (int k = 0; k < 2; k++) {
            uint32_t a0_, a1_, a2_, a3_;
            asm volatile("ld.shared.v4.b32 {%0,%1,%2,%3}, [%4];"
                         : "=r"(a0_), "=r"(a1_), "=r"(a2_), "=r"(a3_)
                         : "r"(buf + warp * 1024 + k * 512 + lane * 16));
            float4 w4;
            w4.x = __uint_as_float(a0_); w4.y = __uint_as_float(a1_);
            w4.z = __uint_as_float(a2_); w4.w = __uint_as_float(a3_);
            int j = s * STAGE_J + warp * 8 + k * 4 + jo;
            float  a  = __ldg(Arow + j);          // L1-hot (prologue B)
            float4 xv = x1p[j * 8 + fq];          // fully coalesced 512B/warp
            acc.x = fmaf(a * w4.x, xv.x, acc.x);
            acc.y = fmaf(a * w4.y, xv.y, acc.y);
            acc.z = fmaf(a * w4.z, xv.z, acc.z);
            acc.w = fmaf(a * w4.w, xv.w, acc.w);
        }
        // no __syncthreads: buffers are never reused
    }

    // reduce across the 4 lanes sharing a feature-quad (xor 8, 16)
    #pragma unroll
    for (int o = 8; o <= 16; o <<= 1) {
        acc.x += __shfl_xor_sync(FULL, acc.x, o);
        acc.y += __shfl_xor_sync(FULL, acc.y, o);
        acc.z += __shfl_xor_sync(FULL, acc.z, o);
        acc.w += __shfl_xor_sync(FULL, acc.w, o);
    }
    if (lane < 8) {
        sacc[warp][lane * 4 + 0] = acc.x;
        sacc[warp][lane * 4 + 1] = acc.y;
        sacc[warp][lane * 4 + 2] = acc.z;
        sacc[warp][lane * 4 + 3] = acc.w;
    }
    __syncthreads();

    // block owns the full row: plain read-modify-write (prep stored xs here)
    if (tid < F_) {
        float ssum = 0.0f;
        #pragma unroll
        for (int w8 = 0; w8 < 8; w8++) ssum += sacc[w8][tid];
        float* dst = outX2 + (size_t)bi * F_ + tid;
        *dst = fmaf(ssum, s_inv, *dst);
    }
    // bulk stores drain at kernel completion
}

// ---------------------------------------------------------------------------
// Launch. Inputs (metadata order): A, W, x, Wn1, bn1, Wn2, bn2, Ws1, bs1,
// Ws2, bs2. Output: [W (B*N*N*F) | x2 (B*N*F)] as float32.
// agg launched with PDL so its prologue (8 TMA fills + A row-sum) overlaps
// prep's tail; the grid-dependency sync orders g_x1/outX2.
// ---------------------------------------------------------------------------
extern "C" void kernel_launch(void* const* d_in, const int* in_sizes, int n_in,
                              void* d_out, int out_size) {
    const float* A   = (const float*)d_in[0];
    const float* W   = (const float*)d_in[1];
    const float* x   = (const float*)d_in[2];
    const float* Wn1 = (const float*)d_in[3];
    const float* bn1 = (const float*)d_in[4];
    const float* Wn2 = (const float*)d_in[5];
    const float* bn2 = (const float*)d_in[6];
    const float* Ws1 = (const float*)d_in[7];
    const float* bs1 = (const float*)d_in[8];
    const float* Ws2 = (const float*)d_in[9];
    const float* bs2 = (const float*)d_in[10];

    float* out   = (float*)d_out;
    float* outW  = out;
    float* outX2 = out + (size_t)B_ * N_ * N_ * F_;

    prep_kernel<<<BN_ / 8, 256>>>(x, Wn1, bn1, Wn2, bn2,
                                  Ws1, bs1, Ws2, bs2, outX2);

    cudaLaunchConfig_t cfg = {};
    cfg.gridDim  = dim3(BN_, 1, 1);
    cfg.blockDim = dim3(256, 1, 1);
    cfg.dynamicSmemBytes = 0;
    cfg.stream = 0;
    cudaLaunchAttribute attr[1];
    attr[0].id = cudaLaunchAttributeProgrammaticStreamSerialization;
    attr[0].val.programmaticStreamSerializationAllowed = 1;
    cfg.attrs = attr;
    cfg.numAttrs = 1;
    cudaLaunchKernelEx(&cfg, agg_kernel, A, W, outW, outX2);
}